// round 1
// baseline (speedup 1.0000x reference)
#include <cuda_runtime.h>

// Problem constants (fixed by the dataset): B=16384, F=256, T=512, D=7, C=4
#define N_FEATS     256
#define N_TREES     512
#define DEPTH       7
#define TOTAL_NODES 130048      // T * (2^(D+1) - 2)
#define N_LEAVES    131072      // T * 2^(D+1)

#define TPB            256
#define WARPS_PER_CTA  8
#define SAMPLES_PER_CTA 32
#define TREES_PER_WARP (N_TREES / WARPS_PER_CTA)   // 64
#define NT             8        // concurrent tree traversals per thread (ILP)

#define XS_STRIDE 257           // padded row stride to spread LDS banks

// Fused (feature_id, bias) table: one LDG.64 per level instead of two LDG.32.
// __device__ global scratch (no allocation — allowed).
__device__ int2 g_combined[TOTAL_NODES];

__global__ void pack_kernel(const int* __restrict__ nodes,
                            const float* __restrict__ biases) {
    int i = blockIdx.x * blockDim.x + threadIdx.x;
    if (i < TOTAL_NODES) {
        g_combined[i] = make_int2(nodes[i], __float_as_int(biases[i]));
    }
}

__global__ __launch_bounds__(TPB) void tree_kernel(
    const float*  __restrict__ x,            // (B, 256)
    const int*    __restrict__ root_nodes,   // (T,)
    const float*  __restrict__ root_biases,  // (T,)
    const int*    __restrict__ tree_indices, // (T,) = 2*t
    const float4* __restrict__ leaf,         // (T*256, 4) as float4
    float4*       __restrict__ out)          // (B, 4) as float4
{
    __shared__ float xs[SAMPLES_PER_CTA * XS_STRIDE];          // 32 KB + pad
    __shared__ float red[WARPS_PER_CTA][SAMPLES_PER_CTA][4];   // 4 KB

    const int tid  = threadIdx.x;
    const int lane = tid & 31;
    const int w    = tid >> 5;
    const int s0   = blockIdx.x * SAMPLES_PER_CTA;

    // Stage 32 sample rows of x into shared (coalesced).
    #pragma unroll
    for (int i = tid; i < SAMPLES_PER_CTA * N_FEATS; i += TPB) {
        int r = i >> 8;          // sample within CTA
        int c = i & (N_FEATS - 1);
        xs[r * XS_STRIDE + c] = x[(s0 + r) * N_FEATS + c];
    }
    __syncthreads();

    const float* myrow = xs + lane * XS_STRIDE;   // lane == local sample

    float a0 = 0.f, a1 = 0.f, a2 = 0.f, a3 = 0.f;
    const int tbase = w * TREES_PER_WARP;

    for (int tt = 0; tt < TREES_PER_WARP; tt += NT) {
        int idx[NT];

        // Root level: uniform per-tree metadata (broadcast loads).
        #pragma unroll
        for (int j = 0; j < NT; j++) {
            int t = tbase + tt + j;
            int   rf = __ldg(&root_nodes[t]);
            float rb = __ldg(&root_biases[t]);
            int   ti = __ldg(&tree_indices[t]);
            idx[j] = ti + (myrow[rf] < rb ? 1 : 0);
        }

        // Levels 1..7. Level-l block starts at T*(2^l - 2); idx is GLOBAL
        // within the level (matches reference).
        int off = 0;
        #pragma unroll
        for (int l = 1; l <= DEPTH; l++) {
            #pragma unroll
            for (int j = 0; j < NT; j++) {
                int2 e = __ldg(&g_combined[off + idx[j]]);      // one LDG.64
                float f = myrow[e.x];                           // LDS
                idx[j] = 2 * idx[j] + (f < __int_as_float(e.y) ? 1 : 0);
            }
            off += N_TREES << l;
        }

        // Leaf accumulate (one LDG.128 per tree).
        #pragma unroll
        for (int j = 0; j < NT; j++) {
            float4 v = __ldg(&leaf[idx[j]]);
            a0 += v.x; a1 += v.y; a2 += v.z; a3 += v.w;
        }
    }

    // Deterministic cross-warp reduction (no atomics -> bit-stable output).
    red[w][lane][0] = a0;
    red[w][lane][1] = a1;
    red[w][lane][2] = a2;
    red[w][lane][3] = a3;
    __syncthreads();

    if (w == 0) {
        float4 r = make_float4(0.f, 0.f, 0.f, 0.f);
        #pragma unroll
        for (int ww = 0; ww < WARPS_PER_CTA; ww++) {
            r.x += red[ww][lane][0];
            r.y += red[ww][lane][1];
            r.z += red[ww][lane][2];
            r.w += red[ww][lane][3];
        }
        out[s0 + lane] = r;
    }
}

extern "C" void kernel_launch(void* const* d_in, const int* in_sizes, int n_in,
                              void* d_out, int out_size) {
    const float* x            = (const float*)d_in[0];
    const int*   root_nodes   = (const int*)  d_in[1];
    const float* root_biases  = (const float*)d_in[2];
    const int*   tree_indices = (const int*)  d_in[3];
    const int*   nodes_flat   = (const int*)  d_in[4];
    const float* biases_flat  = (const float*)d_in[5];
    const float4* leaf        = (const float4*)d_in[6];
    float4* out               = (float4*)d_out;

    const int B = in_sizes[0] / N_FEATS;   // 16384

    pack_kernel<<<(TOTAL_NODES + TPB - 1) / TPB, TPB>>>(nodes_flat, biases_flat);
    tree_kernel<<<B / SAMPLES_PER_CTA, TPB>>>(x, root_nodes, root_biases,
                                              tree_indices, leaf, out);
}

// round 2
// speedup vs baseline: 1.0873x; 1.0873x over previous
#include <cuda_runtime.h>

// Problem constants (fixed by the dataset): B=16384, F=256, T=512, D=7, C=4
#define N_FEATS     256
#define N_TREES     512
#define DEPTH       7
#define TOTAL_NODES 130048      // T * (2^(D+1) - 2)
#define MAX_B       16384

#define TPB             256
#define WARPS_PER_CTA   8
#define SAMPLES_PER_CTA 32
#define HALVES          2
#define TREES_PER_HALF  (N_TREES / HALVES)                 // 256
#define TREES_PER_WARP  (TREES_PER_HALF / WARPS_PER_CTA)   // 32
#define NT              8        // concurrent tree traversals per thread (ILP)

#define XS_STRIDE 257            // padded row stride to spread LDS banks

// Fused (feature_id, bias) table: one LDG.64 per level instead of two LDG.32.
__device__ int2 g_combined[TOTAL_NODES];
// Per-half partial sums (float4 per sample).
__device__ float4 g_part[HALVES * MAX_B];

__global__ void pack_kernel(const int* __restrict__ nodes,
                            const float* __restrict__ biases) {
    int i = blockIdx.x * blockDim.x + threadIdx.x;
    if (i < TOTAL_NODES) {
        g_combined[i] = make_int2(nodes[i], __float_as_int(biases[i]));
    }
}

__global__ __launch_bounds__(TPB) void tree_kernel(
    const float*  __restrict__ x,            // (B, 256)
    const int*    __restrict__ root_nodes,   // (T,)
    const float*  __restrict__ root_biases,  // (T,)
    const int*    __restrict__ tree_indices, // (T,) = 2*t
    const float4* __restrict__ leaf,         // (T*256, 4) as float4
    int B)
{
    // xs is reused as the cross-warp reduction buffer after traversal.
    __shared__ float xs[SAMPLES_PER_CTA * XS_STRIDE];   // 32.9 KB

    const int tid  = threadIdx.x;
    const int lane = tid & 31;
    const int w    = tid >> 5;
    const int s0   = blockIdx.x * SAMPLES_PER_CTA;
    const int half = blockIdx.y;

    // Stage 32 sample rows of x into shared (coalesced).
    #pragma unroll
    for (int i = tid; i < SAMPLES_PER_CTA * N_FEATS; i += TPB) {
        int r = i >> 8;          // sample within CTA
        int c = i & (N_FEATS - 1);
        xs[r * XS_STRIDE + c] = x[(s0 + r) * N_FEATS + c];
    }
    __syncthreads();

    const float* myrow = xs + lane * XS_STRIDE;   // lane == local sample

    float a0 = 0.f, a1 = 0.f, a2 = 0.f, a3 = 0.f;
    const int tbase = half * TREES_PER_HALF + w * TREES_PER_WARP;

    for (int tt = 0; tt < TREES_PER_WARP; tt += NT) {
        int idx[NT];

        // Root level: uniform per-tree metadata (broadcast loads).
        #pragma unroll
        for (int j = 0; j < NT; j++) {
            int t = tbase + tt + j;
            int   rf = __ldg(&root_nodes[t]);
            float rb = __ldg(&root_biases[t]);
            int   ti = __ldg(&tree_indices[t]);
            idx[j] = ti + (myrow[rf] < rb ? 1 : 0);
        }

        // Levels 1..7: level-l block starts at T*(2^l - 2); idx is GLOBAL
        // within the level (matches reference).
        int off = 0;
        #pragma unroll
        for (int l = 1; l <= DEPTH; l++) {
            #pragma unroll
            for (int j = 0; j < NT; j++) {
                int2 e = __ldg(&g_combined[off + idx[j]]);      // one LDG.64
                float f = myrow[e.x];                           // LDS
                idx[j] = 2 * idx[j] + (f < __int_as_float(e.y) ? 1 : 0);
            }
            off += N_TREES << l;
        }

        // Leaf accumulate (one LDG.128 per tree).
        #pragma unroll
        for (int j = 0; j < NT; j++) {
            float4 v = __ldg(&leaf[idx[j]]);
            a0 += v.x; a1 += v.y; a2 += v.z; a3 += v.w;
        }
    }

    // Deterministic cross-warp reduction, reusing xs as scratch.
    __syncthreads();                       // all warps done reading xs
    float* red = xs;                       // [warp][lane][4]
    red[(w * SAMPLES_PER_CTA + lane) * 4 + 0] = a0;
    red[(w * SAMPLES_PER_CTA + lane) * 4 + 1] = a1;
    red[(w * SAMPLES_PER_CTA + lane) * 4 + 2] = a2;
    red[(w * SAMPLES_PER_CTA + lane) * 4 + 3] = a3;
    __syncthreads();

    if (w == 0) {
        float4 r = make_float4(0.f, 0.f, 0.f, 0.f);
        #pragma unroll
        for (int ww = 0; ww < WARPS_PER_CTA; ww++) {
            const float* p = red + (ww * SAMPLES_PER_CTA + lane) * 4;
            r.x += p[0]; r.y += p[1]; r.z += p[2]; r.w += p[3];
        }
        g_part[half * B + s0 + lane] = r;
    }
}

__global__ void reduce_kernel(float4* __restrict__ out, int B) {
    int i = blockIdx.x * blockDim.x + threadIdx.x;
    if (i < B) {
        float4 a = g_part[i];
        float4 b = g_part[B + i];
        out[i] = make_float4(a.x + b.x, a.y + b.y, a.z + b.z, a.w + b.w);
    }
}

extern "C" void kernel_launch(void* const* d_in, const int* in_sizes, int n_in,
                              void* d_out, int out_size) {
    const float* x            = (const float*)d_in[0];
    const int*   root_nodes   = (const int*)  d_in[1];
    const float* root_biases  = (const float*)d_in[2];
    const int*   tree_indices = (const int*)  d_in[3];
    const int*   nodes_flat   = (const int*)  d_in[4];
    const float* biases_flat  = (const float*)d_in[5];
    const float4* leaf        = (const float4*)d_in[6];
    float4* out               = (float4*)d_out;

    const int B = in_sizes[0] / N_FEATS;   // 16384

    // Nudge the L1/shared carveout toward max shared so 6 CTAs/SM fit.
    static int carveout_set = 0;
    cudaFuncSetAttribute(tree_kernel,
                         cudaFuncAttributePreferredSharedMemoryCarveout, 100);
    (void)carveout_set;

    pack_kernel<<<(TOTAL_NODES + TPB - 1) / TPB, TPB>>>(nodes_flat, biases_flat);

    dim3 grid(B / SAMPLES_PER_CTA, HALVES);
    tree_kernel<<<grid, TPB>>>(x, root_nodes, root_biases, tree_indices, leaf, B);

    reduce_kernel<<<(B + TPB - 1) / TPB, TPB>>>(out, B);
}